// round 1
// baseline (speedup 1.0000x reference)
#include <cuda_runtime.h>
#include <cuda_bf16.h>

// HopfieldTSP: x_1000 = sign(w @ x0) because x1 = sign(w@x0) is a provable
// fixed point: w[i,i] = 2*rowsum_i dominates (margin rowsum_i ~ 4096 >> fp32
// rounding) since adj >= 0 and |x1_j| <= 1. So one fused pass over adj
// computes rowsum_i and dot_i = (adj@x0)_i simultaneously, then
//   s_i = (2*rowsum_i + adj_ii)*x0_i - dot_i ;  out_i = sign(s_i).
// Single read of 256 MB -> HBM-bound, ~37 us floor.

#define N_CITIES 8192
#define ROWS_PER_BLOCK 8
#define THREADS (ROWS_PER_BLOCK * 32)

__global__ void __launch_bounds__(THREADS)
hopfield_fused_kernel(const float* __restrict__ adj,
                      const float* __restrict__ x,
                      float* __restrict__ out) {
    __shared__ float xs[N_CITIES];  // 32 KB

    // Stage x into shared memory (vectorized).
    const float4* x4 = reinterpret_cast<const float4*>(x);
    float4* xs4 = reinterpret_cast<float4*>(xs);
    for (int i = threadIdx.x; i < N_CITIES / 4; i += THREADS) {
        xs4[i] = x4[i];
    }
    __syncthreads();

    const int warp = threadIdx.x >> 5;
    const int lane = threadIdx.x & 31;
    const int row  = blockIdx.x * ROWS_PER_BLOCK + warp;

    const float4* arow = reinterpret_cast<const float4*>(adj + (size_t)row * N_CITIES);

    // Each lane: 64 float4 (1 KB) strided across the row. Unroll to batch
    // LDGs up front for MLP (DRAM latency ~577 cyc @ MLP=1).
    float rs = 0.0f;   // rowsum partial
    float dot = 0.0f;  // (adj @ x) partial
    #pragma unroll 8
    for (int j = lane; j < N_CITIES / 4; j += 32) {
        float4 a  = arow[j];
        float4 xv = xs4[j];
        rs  += (a.x + a.y) + (a.z + a.w);
        dot += a.x * xv.x + a.y * xv.y + a.z * xv.z + a.w * xv.w;
    }

    // Warp reduction of the (rs, dot) pair.
    #pragma unroll
    for (int o = 16; o > 0; o >>= 1) {
        rs  += __shfl_xor_sync(0xFFFFFFFFu, rs, o);
        dot += __shfl_xor_sync(0xFFFFFFFFu, dot, o);
    }

    if (lane == 0) {
        float aii = adj[(size_t)row * N_CITIES + row];
        float xi  = xs[row];
        float s   = (2.0f * rs + aii) * xi - dot;
        out[row] = (s > 0.0f) ? 1.0f : ((s < 0.0f) ? -1.0f : 0.0f);
    }
}

extern "C" void kernel_launch(void* const* d_in, const int* in_sizes, int n_in,
                              void* d_out, int out_size) {
    const float* adj = (const float*)d_in[0];   // [8192, 8192] fp32 row-major
    const float* x   = (const float*)d_in[1];   // [8192] fp32
    float* out       = (float*)d_out;           // [8192] fp32

    const int blocks = N_CITIES / ROWS_PER_BLOCK;  // 1024
    hopfield_fused_kernel<<<blocks, THREADS>>>(adj, x, out);
}

// round 2
// speedup vs baseline: 1.2541x; 1.2541x over previous
#include <cuda_runtime.h>
#include <cuda_bf16.h>

// HopfieldTSP: x_1000 = sign(w @ x0). Iterations 2..1000 are a provable fixed
// point (diagonal 2*rowsum_i ~ 8192 dominates |sum adj_ij * (+-1)| <= rowsum_i),
// so one fused pass computes rowsum_i and dot_i = (adj@x0)_i, then
//   s_i = (2*rowsum_i + adj_ii)*x0_i - dot_i ;  out_i = sign(s_i).
//
// R2: single-wave residency. 512-thread blocks (16 rows each) -> grid=512.
// __launch_bounds__(512,4) caps regs at 32 -> 4 blocks/SM -> 64 warps (100%
// occ), capacity 148*4=592 >= 512 -> ONE wave, no latency-bound tail.

#define N_CITIES 8192
#define ROWS_PER_BLOCK 16
#define THREADS (ROWS_PER_BLOCK * 32)   // 512

__global__ void __launch_bounds__(THREADS, 4)
hopfield_fused_kernel(const float* __restrict__ adj,
                      const float* __restrict__ x,
                      float* __restrict__ out) {
    __shared__ float xs[N_CITIES];  // 32 KB, shared by 16 warps

    // Stage x into shared memory (vectorized, 4 float4 per thread).
    const float4* x4 = reinterpret_cast<const float4*>(x);
    float4* xs4 = reinterpret_cast<float4*>(xs);
    #pragma unroll
    for (int i = threadIdx.x; i < N_CITIES / 4; i += THREADS) {
        xs4[i] = x4[i];
    }
    __syncthreads();

    const int warp = threadIdx.x >> 5;
    const int lane = threadIdx.x & 31;
    const int row  = blockIdx.x * ROWS_PER_BLOCK + warp;

    const float4* arow = reinterpret_cast<const float4*>(adj + (size_t)row * N_CITIES);

    // 64 trips of LDG.128 per lane; unroll 4 keeps us under 32 regs while
    // giving MLP=4 per warp (64 warps/SM -> ample outstanding bytes).
    float rs = 0.0f;   // rowsum partial
    float dot = 0.0f;  // (adj @ x0) partial
    #pragma unroll 4
    for (int j = lane; j < N_CITIES / 4; j += 32) {
        float4 a  = arow[j];
        float4 xv = xs4[j];
        rs  += (a.x + a.y) + (a.z + a.w);
        dot += a.x * xv.x + a.y * xv.y + a.z * xv.z + a.w * xv.w;
    }

    // Warp reduction of the (rs, dot) pair.
    #pragma unroll
    for (int o = 16; o > 0; o >>= 1) {
        rs  += __shfl_xor_sync(0xFFFFFFFFu, rs, o);
        dot += __shfl_xor_sync(0xFFFFFFFFu, dot, o);
    }

    if (lane == 0) {
        float aii = __ldg(adj + (size_t)row * N_CITIES + row);
        float xi  = xs[row];
        float s   = (2.0f * rs + aii) * xi - dot;
        out[row] = (s > 0.0f) ? 1.0f : ((s < 0.0f) ? -1.0f : 0.0f);
    }
}

extern "C" void kernel_launch(void* const* d_in, const int* in_sizes, int n_in,
                              void* d_out, int out_size) {
    const float* adj = (const float*)d_in[0];   // [8192, 8192] fp32 row-major
    const float* x   = (const float*)d_in[1];   // [8192] fp32
    float* out       = (float*)d_out;           // [8192] fp32

    const int blocks = N_CITIES / ROWS_PER_BLOCK;  // 512 — one full wave
    hopfield_fused_kernel<<<blocks, THREADS>>>(adj, x, out);
}